// round 1
// baseline (speedup 1.0000x reference)
#include <cuda_runtime.h>
#include <cstdint>

// Problem dims
#define B_N    4096
#define U_DIM  256
#define D_DIM  64
#define KIN    320      // U_DIM + D_DIM
#define H_DIM  8192
#define ORD    4096     // H_DIM / 2
#define Y_DIM  256
#define DELTA_F 0.1f

// G-GEMM split-K config
#define SPLITS 32
#define KCHUNK 256      // H_DIM / SPLITS
#define BM 64
#define BN 64
#define KT 16
#define SPAD 68         // 64 + 4 pad, keeps 16B alignment (68*4 % 16 == 0)

// ---------------- scratch (static device globals; no allocation) ----------------
__device__ float g_Bt[H_DIM * KIN];            // (T o B_w)  [H][320]   10.5 MB
__device__ float g_rec[H_DIM];                 // rotated h
__device__ float g_Gpart[SPLITS][Y_DIM * KIN]; // split-K partials       10.5 MB
__device__ float g_G[Y_DIM * KIN];             // G [256][320]
__device__ float g_y0[Y_DIM];

// ---------------- kernel 1: fold the 2x2 rotation map into B_w ----------------
__global__ void prep_kernel(const float* __restrict__ Bw,
                            const float* __restrict__ om,
                            const float* __restrict__ h) {
    int idx = blockIdx.x * blockDim.x + threadIdx.x;
    if (idx >= ORD * KIN) return;
    int j = idx / KIN;
    int n = idx - j * KIN;
    float w = om[j];
    float s, c;
    sincosf(w * DELTA_F, &s, &c);
    float cm1 = c - 1.0f;
    float inv = 1.0f / w;
    float b0 = Bw[(2 * j) * KIN + n];
    float b1 = Bw[(2 * j + 1) * KIN + n];
    g_Bt[(2 * j) * KIN + n]     = (s * b0 - cm1 * b1) * inv;
    g_Bt[(2 * j + 1) * KIN + n] = (cm1 * b0 + s * b1) * inv;
    if (n == 0) {
        float h0 = h[2 * j], h1 = h[2 * j + 1];
        g_rec[2 * j]     =  c * h0 + s * h1;
        g_rec[2 * j + 1] = -s * h0 + c * h1;
    }
}

// packed-f32x2 FMA helpers
__device__ __forceinline__ unsigned long long pack_dup(float a) {
    unsigned long long d;
    asm("mov.b64 %0, {%1, %1};" : "=l"(d) : "r"(__float_as_uint(a)));
    return d;
}
__device__ __forceinline__ void ffma2(unsigned long long& acc,
                                      unsigned long long a,
                                      unsigned long long b) {
    asm("fma.rn.f32x2 %0, %1, %2, %0;" : "+l"(acc) : "l"(a), "l"(b));
}

// ---------------- kernel 2: G partials = C_w(256x8192) @ Bt(8192x320), split-K ----------------
__global__ __launch_bounds__(256) void gemmG_kernel(const float* __restrict__ Cw) {
    __shared__ float As[KT][SPAD];   // As[kk][m]  (transposed C_w tile)
    __shared__ float Bs[KT][SPAD];   // Bs[kk][n]
    int t = threadIdx.x;
    int n0 = blockIdx.x * BN;                 // 0..256 over KIN
    int m0 = blockIdx.y * BM;                 // 0..192 over Y_DIM
    int kbase = blockIdx.z * KCHUNK;
    int tm = t >> 4, tn = t & 15;             // 16x16 thread grid, 4x4 tile each
    int arow = t >> 2, akq = t & 3;           // A-load mapping
    int bkk = t >> 4, bnq = t & 15;           // B-load mapping

    unsigned long long acc[4][2];
#pragma unroll
    for (int i = 0; i < 4; i++) { acc[i][0] = 0ull; acc[i][1] = 0ull; }

    for (int kt = 0; kt < KCHUNK; kt += KT) {
        int k0 = kbase + kt;
        __syncthreads();
        float4 av = *(const float4*)&Cw[(m0 + arow) * H_DIM + k0 + akq * 4];
        As[akq * 4 + 0][arow] = av.x;
        As[akq * 4 + 1][arow] = av.y;
        As[akq * 4 + 2][arow] = av.z;
        As[akq * 4 + 3][arow] = av.w;
        *(float4*)&Bs[bkk][bnq * 4] =
            *(const float4*)&g_Bt[(k0 + bkk) * KIN + n0 + bnq * 4];
        __syncthreads();
#pragma unroll
        for (int kk = 0; kk < KT; kk++) {
            unsigned long long bp0 = *(const unsigned long long*)&Bs[kk][tn * 4];
            unsigned long long bp1 = *(const unsigned long long*)&Bs[kk][tn * 4 + 2];
#pragma unroll
            for (int i = 0; i < 4; i++) {
                unsigned long long ap = pack_dup(As[kk][tm * 4 + i]);
                ffma2(acc[i][0], ap, bp0);
                ffma2(acc[i][1], ap, bp1);
            }
        }
    }
    float* out = &g_Gpart[blockIdx.z][0];
#pragma unroll
    for (int i = 0; i < 4; i++) {
        int m = m0 + tm * 4 + i;
        *(unsigned long long*)&out[m * KIN + n0 + tn * 4]     = acc[i][0];
        *(unsigned long long*)&out[m * KIN + n0 + tn * 4 + 2] = acc[i][1];
    }
}

// ---------------- kernel 3: deterministic split-K reduction ----------------
__global__ void reduceG_kernel() {
    int idx = blockIdx.x * blockDim.x + threadIdx.x;
    if (idx >= Y_DIM * KIN) return;
    float s = 0.0f;
#pragma unroll
    for (int p = 0; p < SPLITS; p++) s += g_Gpart[p][idx];
    g_G[idx] = s;
}

// ---------------- kernel 4: y0 = C_w @ rec ----------------
__global__ void y0_kernel(const float* __restrict__ Cw) {
    __shared__ float red[256];
    int m = blockIdx.x;
    float s = 0.0f;
    for (int hx = threadIdx.x; hx < H_DIM; hx += 256)
        s += Cw[m * H_DIM + hx] * g_rec[hx];
    red[threadIdx.x] = s;
    __syncthreads();
    for (int off = 128; off > 0; off >>= 1) {
        if (threadIdx.x < off) red[threadIdx.x] += red[threadIdx.x + off];
        __syncthreads();
    }
    if (threadIdx.x == 0) g_y0[m] = red[0];
}

// ---------------- kernel 5: y = y0 + udu @ G^T ----------------
__global__ __launch_bounds__(256) void finalY_kernel(const float* __restrict__ u,
                                                     const float* __restrict__ du,
                                                     float* __restrict__ y) {
    __shared__ float As[KT][SPAD];   // As[kk][b]  (transposed udu tile)
    __shared__ float Bs[KT][SPAD];   // Bs[kk][n]  (transposed G tile)
    int t = threadIdx.x;
    int n0 = blockIdx.x * BN;                 // 0..192 over Y_DIM
    int b0 = blockIdx.y * BM;                 // 0..4032 over batch
    int tm = t >> 4, tn = t & 15;
    int arow = t >> 2, akq = t & 3;

    unsigned long long acc[4][2];
#pragma unroll
    for (int i = 0; i < 4; i++) { acc[i][0] = 0ull; acc[i][1] = 0ull; }

    for (int k0 = 0; k0 < KIN; k0 += KT) {
        __syncthreads();
        // A tile: udu[b0+arow][k0 + akq*4 .. +3]; concat boundary 64 is KT-aligned
        float4 av;
        if (k0 < D_DIM)
            av = *(const float4*)&du[(b0 + arow) * D_DIM + k0 + akq * 4];
        else
            av = *(const float4*)&u[(b0 + arow) * U_DIM + (k0 - D_DIM) + akq * 4];
        As[akq * 4 + 0][arow] = av.x;
        As[akq * 4 + 1][arow] = av.y;
        As[akq * 4 + 2][arow] = av.z;
        As[akq * 4 + 3][arow] = av.w;
        // B tile (transpose of G rows): Bs[kk][n] = G[n0+n][k0+kk]
        float4 gv = *(const float4*)&g_G[(n0 + arow) * KIN + k0 + akq * 4];
        Bs[akq * 4 + 0][arow] = gv.x;
        Bs[akq * 4 + 1][arow] = gv.y;
        Bs[akq * 4 + 2][arow] = gv.z;
        Bs[akq * 4 + 3][arow] = gv.w;
        __syncthreads();
#pragma unroll
        for (int kk = 0; kk < KT; kk++) {
            unsigned long long bp0 = *(const unsigned long long*)&Bs[kk][tn * 4];
            unsigned long long bp1 = *(const unsigned long long*)&Bs[kk][tn * 4 + 2];
#pragma unroll
            for (int i = 0; i < 4; i++) {
                unsigned long long ap = pack_dup(As[kk][tm * 4 + i]);
                ffma2(acc[i][0], ap, bp0);
                ffma2(acc[i][1], ap, bp1);
            }
        }
    }
#pragma unroll
    for (int i = 0; i < 4; i++) {
        int bb = b0 + tm * 4 + i;
        int n = n0 + tn * 4;
#pragma unroll
        for (int j = 0; j < 2; j++) {
            float lo = __uint_as_float((unsigned)(acc[i][j] & 0xFFFFFFFFull));
            float hi = __uint_as_float((unsigned)(acc[i][j] >> 32));
            float2 r;
            r.x = lo + g_y0[n + 2 * j];
            r.y = hi + g_y0[n + 2 * j + 1];
            *(float2*)&y[bb * Y_DIM + n + 2 * j] = r;
        }
    }
}

// ---------------- launch ----------------
extern "C" void kernel_launch(void* const* d_in, const int* in_sizes, int n_in,
                              void* d_out, int out_size) {
    // Robust input binding: all 6 element counts are distinct.
    const float *u = nullptr, *du = nullptr, *h = nullptr, *om = nullptr,
                *Bw = nullptr, *Cw = nullptr;
    for (int i = 0; i < n_in; i++) {
        switch (in_sizes[i]) {
            case B_N * U_DIM:  u  = (const float*)d_in[i]; break; // 1048576
            case B_N * D_DIM:  du = (const float*)d_in[i]; break; // 262144
            case H_DIM:        h  = (const float*)d_in[i]; break; // 8192
            case ORD:          om = (const float*)d_in[i]; break; // 4096
            case H_DIM * KIN:  Bw = (const float*)d_in[i]; break; // 2621440
            case Y_DIM * H_DIM: Cw = (const float*)d_in[i]; break; // 2097152
            default: break;
        }
    }
    if (!u || !du || !h || !om || !Bw || !Cw) {
        // fall back to declared order: u, du, h, omega, B_w, C_w
        u  = (const float*)d_in[0];
        du = (const float*)d_in[1];
        h  = (const float*)d_in[2];
        om = (const float*)d_in[3];
        Bw = (const float*)d_in[4];
        Cw = (const float*)d_in[5];
    }
    float* y = (float*)d_out;

    prep_kernel<<<(ORD * KIN + 255) / 256, 256>>>(Bw, om, h);
    gemmG_kernel<<<dim3(KIN / BN, Y_DIM / BM, SPLITS), 256>>>(Cw);
    reduceG_kernel<<<(Y_DIM * KIN + 255) / 256, 256>>>();
    y0_kernel<<<Y_DIM, 256>>>(Cw);
    finalY_kernel<<<dim3(Y_DIM / BN, B_N / BM), 256>>>(u, du, y);
}